// round 13
// baseline (speedup 1.0000x reference)
#include <cuda_runtime.h>
#include <mma.h>
#include <math.h>
#include <stdint.h>

using namespace nvcuda;

// ---------------- problem constants ----------------
constexpr int NNODE = 50000;
constexpr int NEDGE = 800000;
constexpr int FIN   = 256;
constexpr int H1    = 4;
constexpr int F1    = 256;
constexpr int C2    = 64;
constexpr float SLOPE = 0.2f;
constexpr int M_PAD = 50048;   // 128 * 391

// ---------------- scratch ----------------
__device__ float g_xr[(size_t)NNODE * FIN];    // tf32-rounded x
__device__ float g_w1r[FIN * F1];              // tf32-rounded W1
__device__ float g_w2r[F1 * C2];               // tf32-rounded W2
__device__ float g_h1[(size_t)M_PAD * F1];
__device__ float g_hbuf[(size_t)M_PAD * F1];   // tf32-rounded elu(out1+b1)
__device__ float g_h2[(size_t)M_PAD * C2];
__device__ float g_as1[NNODE * H1];
__device__ float g_ad1[NNODE * H1];
__device__ float g_as2[NNODE];
__device__ float g_ad2[NNODE];
__device__ int   g_deg[NNODE];
__device__ int   g_cur[NNODE];
__device__ int   g_offs[NNODE + 1];
__device__ int   g_bsums[64];
__device__ int   g_csr[NEDGE];

__device__ __forceinline__ float leakyr(float v) { return v > 0.f ? v : SLOPE * v; }

__device__ __forceinline__ float to_tf32(float x) {
    uint32_t r;
    asm("cvt.rna.tf32.f32 %0, %1;\n" : "=r"(r) : "f"(x));
    return __uint_as_float(r);
}

// ---------------- operand pre-rounding (rna -> tf32 grid, once) ----------------
__global__ void round_x_kernel(const float* __restrict__ x) {
    int i = blockIdx.x * blockDim.x + threadIdx.x;   // float4 index
    if (i < NNODE * FIN / 4) {
        float4 v = ((const float4*)x)[i];
        float4 r = make_float4(to_tf32(v.x), to_tf32(v.y), to_tf32(v.z), to_tf32(v.w));
        ((float4*)g_xr)[i] = r;
    }
}

__global__ void round_w_kernel(const float* __restrict__ W1, const float* __restrict__ W2) {
    int i = blockIdx.x * blockDim.x + threadIdx.x;
    if (i < FIN * F1) g_w1r[i] = to_tf32(W1[i]);
    if (i < F1 * C2)  g_w2r[i] = to_tf32(W2[i]);
}

// ---------------- CSR construction (5 kernels) ----------------
__global__ void zero_ints_kernel() {
    int i = blockIdx.x * blockDim.x + threadIdx.x;
    if (i < NNODE) g_deg[i] = 0;
}

__global__ void count_deg_kernel(const int* __restrict__ ei) {
    int e = blockIdx.x * blockDim.x + threadIdx.x;
    if (e < NEDGE) {
        int d = ei[NEDGE + e];
        if (d >= 0 && d < NNODE) atomicAdd(&g_deg[d], 1);
    }
}

constexpr int SCAN_T = 1024;
constexpr int SCAN_NB = (NNODE + SCAN_T - 1) / SCAN_T;  // 49

__global__ void scan_block_kernel() {
    __shared__ int sh[SCAN_T];
    int gid = blockIdx.x * SCAN_T + threadIdx.x;
    int v = (gid < NNODE) ? g_deg[gid] : 0;
    sh[threadIdx.x] = v;
    __syncthreads();
    for (int off = 1; off < SCAN_T; off <<= 1) {
        int t = (threadIdx.x >= off) ? sh[threadIdx.x - off] : 0;
        __syncthreads();
        sh[threadIdx.x] += t;
        __syncthreads();
    }
    if (gid < NNODE) g_offs[gid] = sh[threadIdx.x] - v;
    if (threadIdx.x == SCAN_T - 1) g_bsums[blockIdx.x] = sh[threadIdx.x];
}

__global__ void scan_add_kernel() {
    __shared__ int base_sh;
    int t = threadIdx.x;
    if (t == 0) {
        int s = 0;
        for (int i = 0; i < blockIdx.x; i++) s += g_bsums[i];
        base_sh = s;
    }
    __syncthreads();
    int gid = blockIdx.x * SCAN_T + t;
    if (gid < NNODE) {
        int v = g_offs[gid] + base_sh;
        g_offs[gid] = v;
        g_cur[gid] = v;
    }
    if (gid == 0) g_offs[NNODE] = NEDGE;
}

__global__ void scatter_kernel(const int* __restrict__ ei) {
    int e = blockIdx.x * blockDim.x + threadIdx.x;
    if (e < NEDGE) {
        int d = ei[NEDGE + e];
        int s = ei[e];
        if (d >= 0 && d < NNODE && s >= 0 && s < NNODE) {
            int p = atomicAdd(&g_cur[d], 1);
            if (p >= 0 && p < NEDGE) g_csr[p] = s;
        }
    }
}

// ---------------- tf32 wmma GEMM on pre-rounded operands (no in-loop cvt) --------
// MODE 0: A=g_xr,  B=g_w1r, C=g_h1, BN=128, WN=64.
// MODE 1: A=g_hbuf, B=g_w2r, C=g_h2, BN=64,  WN=32.
template <int BN, int WN, int MODE>
__global__ void __launch_bounds__(256)
wmma_gemm_kernel(int M, int K) {
    constexpr int BM = 128, BK = 16, WM = 32;
    constexpr int MI = WM / 16;
    constexpr int NI = WN / 16;
    constexpr int LDA = BK + 4;

    const float* __restrict__ A = (MODE == 0) ? g_xr : g_hbuf;
    const float* __restrict__ B = (MODE == 0) ? g_w1r : g_w2r;
    float* __restrict__ C = (MODE == 0) ? g_h1 : g_h2;

    __shared__ float As[2][BM][LDA];
    __shared__ float Bs[2][BK][BN];

    int tid = threadIdx.x;
    int wid = tid >> 5;
    int warpM = wid & 3;
    int warpN = wid >> 2;
    int rowBase = blockIdx.y * BM;
    int colBase = blockIdx.x * BN;
    int Nt = BN * gridDim.x;

    wmma::fragment<wmma::accumulator, 16, 16, 8, float> c[MI][NI];
#pragma unroll
    for (int i = 0; i < MI; i++)
#pragma unroll
        for (int j = 0; j < NI; j++) wmma::fill_fragment(c[i][j], 0.f);

    constexpr int B_F4 = BK * BN / 4;
    constexpr int B_F4PR = BN / 4;

    auto issue = [&](int buf, int k0) {
#pragma unroll
        for (int li = 0; li < 2; li++) {
            int f4 = tid + li * 256;
            int row = f4 >> 2;
            int col = (f4 & 3) * 4;
            int rg = rowBase + row;
            const float* src = &A[(size_t)(rg < M ? rg : 0) * K + k0 + col];
            uint32_t dst = (uint32_t)__cvta_generic_to_shared(&As[buf][row][col]);
            int sz = (rg < M) ? 16 : 0;
            asm volatile("cp.async.cg.shared.global [%0], [%1], 16, %2;\n"
                         :: "r"(dst), "l"(src), "r"(sz));
        }
#pragma unroll
        for (int li = 0; li < (B_F4 + 255) / 256; li++) {
            int f4 = tid + li * 256;
            if (B_F4 % 256 == 0 || f4 < B_F4) {
                int row = f4 / B_F4PR;
                int col = (f4 % B_F4PR) * 4;
                const float* src = &B[(size_t)(k0 + row) * Nt + colBase + col];
                uint32_t dst = (uint32_t)__cvta_generic_to_shared(&Bs[buf][row][col]);
                asm volatile("cp.async.cg.shared.global [%0], [%1], 16;\n"
                             :: "r"(dst), "l"(src));
            }
        }
        asm volatile("cp.async.commit_group;\n");
    };

    int NT = K / BK;
    issue(0, 0);

    for (int kt = 0; kt < NT; kt++) {
        if (kt + 1 < NT) {
            issue((kt + 1) & 1, (kt + 1) * BK);
            asm volatile("cp.async.wait_group 1;\n");
        } else {
            asm volatile("cp.async.wait_group 0;\n");
        }
        __syncthreads();
        int buf = kt & 1;

#pragma unroll
        for (int kk = 0; kk < BK; kk += 8) {
            wmma::fragment<wmma::matrix_a, 16, 16, 8, wmma::precision::tf32, wmma::row_major> a[MI];
            wmma::fragment<wmma::matrix_b, 16, 16, 8, wmma::precision::tf32, wmma::row_major> b[NI];
#pragma unroll
            for (int i = 0; i < MI; i++)
                wmma::load_matrix_sync(a[i], &As[buf][warpM * WM + i * 16][kk], LDA);
#pragma unroll
            for (int j = 0; j < NI; j++)
                wmma::load_matrix_sync(b[j], &Bs[buf][kk][warpN * WN + j * 16], BN);
#pragma unroll
            for (int i = 0; i < MI; i++)
#pragma unroll
                for (int j = 0; j < NI; j++)
                    wmma::mma_sync(c[i][j], a[i], b[j], c[i][j]);
        }
        __syncthreads();
    }

    int ldc = Nt;
#pragma unroll
    for (int i = 0; i < MI; i++)
#pragma unroll
        for (int j = 0; j < NI; j++) {
            int r = rowBase + warpM * WM + i * 16;
            int cc = colBase + warpN * WN + j * 16;
            wmma::store_matrix_sync(&C[(size_t)r * ldc + cc], c[i][j], ldc, wmma::mem_row_major);
        }
}

// ---------------- attention coefficients (warp per (node,head), coalesced) -------
template <int L>
__global__ void attn_coeff_kernel(const float* __restrict__ atts,
                                  const float* __restrict__ attd) {
    const float* __restrict__ h = (L == 0) ? g_h1 : g_h2;
    float* __restrict__ oS = (L == 0) ? g_as1 : g_as2;
    float* __restrict__ oD = (L == 0) ? g_ad1 : g_ad2;
    const int H = (L == 0) ? H1 : 1;

    int w = (blockIdx.x * blockDim.x + threadIdx.x) >> 5;
    int lane = threadIdx.x & 31;
    if (w >= NNODE * H) return;
    int hh = w % H;
    const float* hp = h + (size_t)w * 64;

    float x1 = hp[lane], x2 = hp[lane + 32];
    float ss = x1 * atts[hh * 64 + lane] + x2 * atts[hh * 64 + lane + 32];
    float sd = x1 * attd[hh * 64 + lane] + x2 * attd[hh * 64 + lane + 32];
#pragma unroll
    for (int o = 16; o; o >>= 1) {
        ss += __shfl_xor_sync(0xFFFFFFFFu, ss, o);
        sd += __shfl_xor_sync(0xFFFFFFFFu, sd, o);
    }
    if (lane == 0) { oS[w] = ss; oD[w] = sd; }
}

// ---------------- layer-1 aggregation (R10-proven; epilogue stores tf32-rounded) --
__global__ void __launch_bounds__(256)
agg1_kernel(const float* __restrict__ b1) {
    int tl = threadIdx.x & 63;
    int g  = threadIdx.x >> 6;
    int n  = blockIdx.x * 4 + g;
    if (n >= NNODE) return;
    int h  = tl >> 4;
    int c4 = tl * 4;
    int beg = g_offs[n], end = g_offs[n + 1];
    float ad = g_ad1[n * H1 + h];

    float wself = __expf(leakyr(g_as1[n * H1 + h] + ad));
    float4 hv = *(const float4*)&g_h1[(size_t)n * F1 + c4];
    float s0 = wself, s1 = 0.f, s2 = 0.f, s3 = 0.f;
    float4 a0 = make_float4(wself * hv.x, wself * hv.y, wself * hv.z, wself * hv.w);
    float4 a1 = make_float4(0.f, 0.f, 0.f, 0.f);
    float4 a2 = make_float4(0.f, 0.f, 0.f, 0.f);
    float4 a3 = make_float4(0.f, 0.f, 0.f, 0.f);

    int i = beg;
    for (; i + 3 < end; i += 4) {
        int sA = g_csr[i], sB = g_csr[i + 1], sC = g_csr[i + 2], sD = g_csr[i + 3];
        float wA = __expf(leakyr(g_as1[sA * H1 + h] + ad));
        float wB = __expf(leakyr(g_as1[sB * H1 + h] + ad));
        float wC = __expf(leakyr(g_as1[sC * H1 + h] + ad));
        float wD = __expf(leakyr(g_as1[sD * H1 + h] + ad));
        float4 hA = *(const float4*)&g_h1[(size_t)sA * F1 + c4];
        float4 hB = *(const float4*)&g_h1[(size_t)sB * F1 + c4];
        float4 hC = *(const float4*)&g_h1[(size_t)sC * F1 + c4];
        float4 hD = *(const float4*)&g_h1[(size_t)sD * F1 + c4];
        s0 += wA; s1 += wB; s2 += wC; s3 += wD;
        a0.x = fmaf(wA, hA.x, a0.x); a0.y = fmaf(wA, hA.y, a0.y);
        a0.z = fmaf(wA, hA.z, a0.z); a0.w = fmaf(wA, hA.w, a0.w);
        a1.x = fmaf(wB, hB.x, a1.x); a1.y = fmaf(wB, hB.y, a1.y);
        a1.z = fmaf(wB, hB.z, a1.z); a1.w = fmaf(wB, hB.w, a1.w);
        a2.x = fmaf(wC, hC.x, a2.x); a2.y = fmaf(wC, hC.y, a2.y);
        a2.z = fmaf(wC, hC.z, a2.z); a2.w = fmaf(wC, hC.w, a2.w);
        a3.x = fmaf(wD, hD.x, a3.x); a3.y = fmaf(wD, hD.y, a3.y);
        a3.z = fmaf(wD, hD.z, a3.z); a3.w = fmaf(wD, hD.w, a3.w);
    }
    for (; i < end; i++) {
        int sA = g_csr[i];
        float wA = __expf(leakyr(g_as1[sA * H1 + h] + ad));
        float4 hA = *(const float4*)&g_h1[(size_t)sA * F1 + c4];
        s0 += wA;
        a0.x = fmaf(wA, hA.x, a0.x); a0.y = fmaf(wA, hA.y, a0.y);
        a0.z = fmaf(wA, hA.z, a0.z); a0.w = fmaf(wA, hA.w, a0.w);
    }
    float inv = 1.f / (s0 + s1 + s2 + s3 + 1e-16f);
    float4 bb = *(const float4*)&b1[c4];
    float o0 = (a0.x + a1.x + a2.x + a3.x) * inv + bb.x;
    float o1 = (a0.y + a1.y + a2.y + a3.y) * inv + bb.y;
    float o2 = (a0.z + a1.z + a2.z + a3.z) * inv + bb.z;
    float o3 = (a0.w + a1.w + a2.w + a3.w) * inv + bb.w;
    // elu, then rna-round to tf32 grid: GEMM2 sees bit-identical operand to
    // the previous in-GEMM cvt scheme.
    float4 r;
    r.x = to_tf32((o0 > 0.f) ? o0 : (__expf(o0) - 1.f));
    r.y = to_tf32((o1 > 0.f) ? o1 : (__expf(o1) - 1.f));
    r.z = to_tf32((o2 > 0.f) ? o2 : (__expf(o2) - 1.f));
    r.w = to_tf32((o3 > 0.f) ? o3 : (__expf(o3) - 1.f));
    *(float4*)&g_hbuf[(size_t)n * F1 + c4] = r;
}

// ---------------- layer-2 aggregation (16 thr/node, 4-way ILP; R10-proven) --------
__global__ void __launch_bounds__(256)
agg2_kernel(const float* __restrict__ b2, float* __restrict__ out) {
    int tl = threadIdx.x & 15;
    int g  = threadIdx.x >> 4;
    int n  = blockIdx.x * 16 + g;
    if (n >= NNODE) return;
    int c4 = tl * 4;
    int beg = g_offs[n], end = g_offs[n + 1];
    float ad = g_ad2[n];

    float wself = __expf(leakyr(g_as2[n] + ad));
    float4 hv = *(const float4*)&g_h2[(size_t)n * C2 + c4];
    float s0 = wself, s1 = 0.f, s2 = 0.f, s3 = 0.f;
    float4 a0 = make_float4(wself * hv.x, wself * hv.y, wself * hv.z, wself * hv.w);
    float4 a1 = make_float4(0.f, 0.f, 0.f, 0.f);
    float4 a2 = make_float4(0.f, 0.f, 0.f, 0.f);
    float4 a3 = make_float4(0.f, 0.f, 0.f, 0.f);

    int i = beg;
    for (; i + 3 < end; i += 4) {
        int sA = g_csr[i], sB = g_csr[i + 1], sC = g_csr[i + 2], sD = g_csr[i + 3];
        float wA = __expf(leakyr(g_as2[sA] + ad));
        float wB = __expf(leakyr(g_as2[sB] + ad));
        float wC = __expf(leakyr(g_as2[sC] + ad));
        float wD = __expf(leakyr(g_as2[sD] + ad));
        float4 hA = *(const float4*)&g_h2[(size_t)sA * C2 + c4];
        float4 hB = *(const float4*)&g_h2[(size_t)sB * C2 + c4];
        float4 hC = *(const float4*)&g_h2[(size_t)sC * C2 + c4];
        float4 hD = *(const float4*)&g_h2[(size_t)sD * C2 + c4];
        s0 += wA; s1 += wB; s2 += wC; s3 += wD;
        a0.x = fmaf(wA, hA.x, a0.x); a0.y = fmaf(wA, hA.y, a0.y);
        a0.z = fmaf(wA, hA.z, a0.z); a0.w = fmaf(wA, hA.w, a0.w);
        a1.x = fmaf(wB, hB.x, a1.x); a1.y = fmaf(wB, hB.y, a1.y);
        a1.z = fmaf(wB, hB.z, a1.z); a1.w = fmaf(wB, hB.w, a1.w);
        a2.x = fmaf(wC, hC.x, a2.x); a2.y = fmaf(wC, hC.y, a2.y);
        a2.z = fmaf(wC, hC.z, a2.z); a2.w = fmaf(wC, hC.w, a2.w);
        a3.x = fmaf(wD, hD.x, a3.x); a3.y = fmaf(wD, hD.y, a3.y);
        a3.z = fmaf(wD, hD.z, a3.z); a3.w = fmaf(wD, hD.w, a3.w);
    }
    for (; i < end; i++) {
        int sA = g_csr[i];
        float wA = __expf(leakyr(g_as2[sA] + ad));
        float4 hA = *(const float4*)&g_h2[(size_t)sA * C2 + c4];
        s0 += wA;
        a0.x = fmaf(wA, hA.x, a0.x); a0.y = fmaf(wA, hA.y, a0.y);
        a0.z = fmaf(wA, hA.z, a0.z); a0.w = fmaf(wA, hA.w, a0.w);
    }
    float inv = 1.f / (s0 + s1 + s2 + s3 + 1e-16f);
    float4 bb = *(const float4*)&b2[c4];
    float o0 = (a0.x + a1.x + a2.x + a3.x) * inv + bb.x;
    float o1 = (a0.y + a1.y + a2.y + a3.y) * inv + bb.y;
    float o2 = (a0.z + a1.z + a2.z + a3.z) * inv + bb.z;
    float o3 = (a0.w + a1.w + a2.w + a3.w) * inv + bb.w;
    float4 r;
    r.x = (o0 > 0.f) ? o0 : (__expf(o0) - 1.f);
    r.y = (o1 > 0.f) ? o1 : (__expf(o1) - 1.f);
    r.z = (o2 > 0.f) ? o2 : (__expf(o2) - 1.f);
    r.w = (o3 > 0.f) ? o3 : (__expf(o3) - 1.f);
    *(float4*)&out[(size_t)n * C2 + c4] = r;
}

// ---------------- launch ----------------
extern "C" void kernel_launch(void* const* d_in, const int* in_sizes, int n_in,
                              void* d_out, int out_size) {
    const float* x    = (const float*)d_in[0];
    const int*   ei   = (const int*)d_in[1];
    const float* W1   = (const float*)d_in[2];
    const float* as1w = (const float*)d_in[3];
    const float* ad1w = (const float*)d_in[4];
    const float* b1   = (const float*)d_in[5];
    const float* W2   = (const float*)d_in[6];
    const float* as2w = (const float*)d_in[7];
    const float* ad2w = (const float*)d_in[8];
    const float* b2   = (const float*)d_in[9];
    float*       out  = (float*)d_out;

    (void)in_sizes; (void)n_in; (void)out_size;

    static cudaStream_t s2 = []() {
        cudaStream_t s; cudaStreamCreateWithFlags(&s, cudaStreamNonBlocking); return s;
    }();
    static cudaEvent_t evFork = []() {
        cudaEvent_t e; cudaEventCreateWithFlags(&e, cudaEventDisableTiming); return e;
    }();
    static cudaEvent_t evJoin = []() {
        cudaEvent_t e; cudaEventCreateWithFlags(&e, cudaEventDisableTiming); return e;
    }();

    // ---- fork: CSR build on s2 overlaps operand-rounding + GEMM1 on main ----
    cudaEventRecord(evFork, 0);
    cudaStreamWaitEvent(s2, evFork, 0);

    // my launches: 1=round_x 2=round_w 3=zero 4=GEMM1 (profiled by ncu slot #6)
    round_x_kernel<<<(NNODE * FIN / 4 + 255) / 256, 256>>>(x);
    round_w_kernel<<<(FIN * F1 + 255) / 256, 256>>>(W1, W2);
    zero_ints_kernel<<<(NNODE + 255) / 256, 256, 0, s2>>>();

    {
        dim3 grid(F1 / 128, M_PAD / 128);   // (2, 391)
        wmma_gemm_kernel<128, 64, 0><<<grid, 256>>>(NNODE, FIN);
    }

    count_deg_kernel<<<(NEDGE + 255) / 256, 256, 0, s2>>>(ei);
    scan_block_kernel<<<SCAN_NB, SCAN_T, 0, s2>>>();
    scan_add_kernel<<<SCAN_NB, SCAN_T, 0, s2>>>();
    scatter_kernel<<<(NEDGE + 255) / 256, 256, 0, s2>>>(ei);
    cudaEventRecord(evJoin, s2);

    attn_coeff_kernel<0><<<(NNODE * H1 + 7) / 8, 256>>>(as1w, ad1w);

    // ---- join: agg1 needs CSR + h1 + coeffs ----
    cudaStreamWaitEvent(0, evJoin, 0);
    agg1_kernel<<<(NNODE + 3) / 4, 256>>>(b1);

    // ---- layer 2 ----
    {
        dim3 grid(1, M_PAD / 128);          // (1, 391)
        wmma_gemm_kernel<64, 32, 1><<<grid, 256>>>(NNODE, F1);
    }
    attn_coeff_kernel<1><<<(NNODE + 7) / 8, 256>>>(as2w, ad2w);
    agg2_kernel<<<(NNODE + 15) / 16, 256>>>(b2, out);
}

// round 14
// speedup vs baseline: 1.0782x; 1.0782x over previous
#include <cuda_runtime.h>
#include <mma.h>
#include <math.h>
#include <stdint.h>

using namespace nvcuda;

// ---------------- problem constants ----------------
constexpr int NNODE = 50000;
constexpr int NEDGE = 800000;
constexpr int FIN   = 256;
constexpr int H1    = 4;
constexpr int F1    = 256;
constexpr int C2    = 64;
constexpr float SLOPE = 0.2f;
constexpr int M_PAD = 50048;   // 128 * 391

// ---------------- scratch ----------------
__device__ float g_xr[(size_t)NNODE * FIN];    // tf32-rounded x
__device__ float g_w1r[FIN * F1];              // tf32-rounded W1
__device__ float g_w2r[F1 * C2];               // tf32-rounded W2
__device__ float g_h1[(size_t)M_PAD * F1];
__device__ float g_hbuf[(size_t)M_PAD * F1];   // tf32-rounded elu(out1+b1)
__device__ float g_h2[(size_t)M_PAD * C2];
__device__ float g_as1[NNODE * H1];
__device__ float g_ad1[NNODE * H1];
__device__ float g_as2[NNODE];
__device__ float g_ad2[NNODE];
__device__ int   g_deg[NNODE];
__device__ int   g_cur[NNODE];
__device__ int   g_offs[NNODE + 1];
__device__ int   g_bsums[64];
__device__ int   g_csr[NEDGE];

__device__ __forceinline__ float leakyr(float v) { return v > 0.f ? v : SLOPE * v; }

__device__ __forceinline__ float to_tf32(float x) {
    uint32_t r;
    asm("cvt.rna.tf32.f32 %0, %1;\n" : "=r"(r) : "f"(x));
    return __uint_as_float(r);
}

// ---------------- operand pre-rounding (rna -> tf32 grid, once) ----------------
__global__ void round_x_kernel(const float* __restrict__ x) {
    int i = blockIdx.x * blockDim.x + threadIdx.x;   // float4 index
    if (i < NNODE * FIN / 4) {
        float4 v = ((const float4*)x)[i];
        float4 r = make_float4(to_tf32(v.x), to_tf32(v.y), to_tf32(v.z), to_tf32(v.w));
        ((float4*)g_xr)[i] = r;
    }
}

__global__ void round_w_kernel(const float* __restrict__ W1, const float* __restrict__ W2) {
    int i = blockIdx.x * blockDim.x + threadIdx.x;
    if (i < FIN * F1) g_w1r[i] = to_tf32(W1[i]);
    if (i < F1 * C2)  g_w2r[i] = to_tf32(W2[i]);
}

// ---------------- CSR construction (5 kernels) ----------------
__global__ void zero_ints_kernel() {
    int i = blockIdx.x * blockDim.x + threadIdx.x;
    if (i < NNODE) g_deg[i] = 0;
}

__global__ void count_deg_kernel(const int* __restrict__ ei) {
    int e = blockIdx.x * blockDim.x + threadIdx.x;
    if (e < NEDGE) {
        int d = ei[NEDGE + e];
        if (d >= 0 && d < NNODE) atomicAdd(&g_deg[d], 1);
    }
}

constexpr int SCAN_T = 1024;
constexpr int SCAN_NB = (NNODE + SCAN_T - 1) / SCAN_T;  // 49

__global__ void scan_block_kernel() {
    __shared__ int sh[SCAN_T];
    int gid = blockIdx.x * SCAN_T + threadIdx.x;
    int v = (gid < NNODE) ? g_deg[gid] : 0;
    sh[threadIdx.x] = v;
    __syncthreads();
    for (int off = 1; off < SCAN_T; off <<= 1) {
        int t = (threadIdx.x >= off) ? sh[threadIdx.x - off] : 0;
        __syncthreads();
        sh[threadIdx.x] += t;
        __syncthreads();
    }
    if (gid < NNODE) g_offs[gid] = sh[threadIdx.x] - v;
    if (threadIdx.x == SCAN_T - 1) g_bsums[blockIdx.x] = sh[threadIdx.x];
}

__global__ void scan_add_kernel() {
    __shared__ int base_sh;
    int t = threadIdx.x;
    if (t == 0) {
        int s = 0;
        for (int i = 0; i < blockIdx.x; i++) s += g_bsums[i];
        base_sh = s;
    }
    __syncthreads();
    int gid = blockIdx.x * SCAN_T + t;
    if (gid < NNODE) {
        int v = g_offs[gid] + base_sh;
        g_offs[gid] = v;
        g_cur[gid] = v;
    }
    if (gid == 0) g_offs[NNODE] = NEDGE;
}

__global__ void scatter_kernel(const int* __restrict__ ei) {
    int e = blockIdx.x * blockDim.x + threadIdx.x;
    if (e < NEDGE) {
        int d = ei[NEDGE + e];
        int s = ei[e];
        if (d >= 0 && d < NNODE && s >= 0 && s < NNODE) {
            int p = atomicAdd(&g_cur[d], 1);
            if (p >= 0 && p < NEDGE) g_csr[p] = s;
        }
    }
}

// ---------------- tf32 wmma GEMM on pre-rounded operands (no in-loop cvt) --------
// __launch_bounds__(256, 2): cap regs at 128 so 2 CTAs/SM (R13 hit 130 regs -> 1 CTA).
// MODE 0: A=g_xr,  B=g_w1r, C=g_h1, BN=128, WN=64.
// MODE 1: A=g_hbuf, B=g_w2r, C=g_h2, BN=64,  WN=32.
template <int BN, int WN, int MODE>
__global__ void __launch_bounds__(256, 2)
wmma_gemm_kernel(int M, int K) {
    constexpr int BM = 128, BK = 16, WM = 32;
    constexpr int MI = WM / 16;
    constexpr int NI = WN / 16;
    constexpr int LDA = BK + 4;

    const float* __restrict__ A = (MODE == 0) ? g_xr : g_hbuf;
    const float* __restrict__ B = (MODE == 0) ? g_w1r : g_w2r;
    float* __restrict__ C = (MODE == 0) ? g_h1 : g_h2;

    __shared__ float As[2][BM][LDA];
    __shared__ float Bs[2][BK][BN];

    int tid = threadIdx.x;
    int wid = tid >> 5;
    int warpM = wid & 3;
    int warpN = wid >> 2;
    int rowBase = blockIdx.y * BM;
    int colBase = blockIdx.x * BN;
    int Nt = BN * gridDim.x;

    wmma::fragment<wmma::accumulator, 16, 16, 8, float> c[MI][NI];
#pragma unroll
    for (int i = 0; i < MI; i++)
#pragma unroll
        for (int j = 0; j < NI; j++) wmma::fill_fragment(c[i][j], 0.f);

    constexpr int B_F4 = BK * BN / 4;
    constexpr int B_F4PR = BN / 4;

    auto issue = [&](int buf, int k0) {
#pragma unroll
        for (int li = 0; li < 2; li++) {
            int f4 = tid + li * 256;
            int row = f4 >> 2;
            int col = (f4 & 3) * 4;
            int rg = rowBase + row;
            const float* src = &A[(size_t)(rg < M ? rg : 0) * K + k0 + col];
            uint32_t dst = (uint32_t)__cvta_generic_to_shared(&As[buf][row][col]);
            int sz = (rg < M) ? 16 : 0;
            asm volatile("cp.async.cg.shared.global [%0], [%1], 16, %2;\n"
                         :: "r"(dst), "l"(src), "r"(sz));
        }
#pragma unroll
        for (int li = 0; li < (B_F4 + 255) / 256; li++) {
            int f4 = tid + li * 256;
            if (B_F4 % 256 == 0 || f4 < B_F4) {
                int row = f4 / B_F4PR;
                int col = (f4 % B_F4PR) * 4;
                const float* src = &B[(size_t)(k0 + row) * Nt + colBase + col];
                uint32_t dst = (uint32_t)__cvta_generic_to_shared(&Bs[buf][row][col]);
                asm volatile("cp.async.cg.shared.global [%0], [%1], 16;\n"
                             :: "r"(dst), "l"(src));
            }
        }
        asm volatile("cp.async.commit_group;\n");
    };

    int NT = K / BK;
    issue(0, 0);

    for (int kt = 0; kt < NT; kt++) {
        if (kt + 1 < NT) {
            issue((kt + 1) & 1, (kt + 1) * BK);
            asm volatile("cp.async.wait_group 1;\n");
        } else {
            asm volatile("cp.async.wait_group 0;\n");
        }
        __syncthreads();
        int buf = kt & 1;

#pragma unroll
        for (int kk = 0; kk < BK; kk += 8) {
            wmma::fragment<wmma::matrix_a, 16, 16, 8, wmma::precision::tf32, wmma::row_major> a[MI];
            wmma::fragment<wmma::matrix_b, 16, 16, 8, wmma::precision::tf32, wmma::row_major> b[NI];
#pragma unroll
            for (int i = 0; i < MI; i++)
                wmma::load_matrix_sync(a[i], &As[buf][warpM * WM + i * 16][kk], LDA);
#pragma unroll
            for (int j = 0; j < NI; j++)
                wmma::load_matrix_sync(b[j], &Bs[buf][kk][warpN * WN + j * 16], BN);
#pragma unroll
            for (int i = 0; i < MI; i++)
#pragma unroll
                for (int j = 0; j < NI; j++)
                    wmma::mma_sync(c[i][j], a[i], b[j], c[i][j]);
        }
        __syncthreads();
    }

    int ldc = Nt;
#pragma unroll
    for (int i = 0; i < MI; i++)
#pragma unroll
        for (int j = 0; j < NI; j++) {
            int r = rowBase + warpM * WM + i * 16;
            int cc = colBase + warpN * WN + j * 16;
            wmma::store_matrix_sync(&C[(size_t)r * ldc + cc], c[i][j], ldc, wmma::mem_row_major);
        }
}

// ---------------- attention coefficients (warp per (node,head), coalesced) -------
template <int L>
__global__ void attn_coeff_kernel(const float* __restrict__ atts,
                                  const float* __restrict__ attd) {
    const float* __restrict__ h = (L == 0) ? g_h1 : g_h2;
    float* __restrict__ oS = (L == 0) ? g_as1 : g_as2;
    float* __restrict__ oD = (L == 0) ? g_ad1 : g_ad2;
    const int H = (L == 0) ? H1 : 1;

    int w = (blockIdx.x * blockDim.x + threadIdx.x) >> 5;
    int lane = threadIdx.x & 31;
    if (w >= NNODE * H) return;
    int hh = w % H;
    const float* hp = h + (size_t)w * 64;

    float x1 = hp[lane], x2 = hp[lane + 32];
    float ss = x1 * atts[hh * 64 + lane] + x2 * atts[hh * 64 + lane + 32];
    float sd = x1 * attd[hh * 64 + lane] + x2 * attd[hh * 64 + lane + 32];
#pragma unroll
    for (int o = 16; o; o >>= 1) {
        ss += __shfl_xor_sync(0xFFFFFFFFu, ss, o);
        sd += __shfl_xor_sync(0xFFFFFFFFu, sd, o);
    }
    if (lane == 0) { oS[w] = ss; oD[w] = sd; }
}

// ---------------- layer-1 aggregation (R10-proven; epilogue stores tf32-rounded) --
__global__ void __launch_bounds__(256)
agg1_kernel(const float* __restrict__ b1) {
    int tl = threadIdx.x & 63;
    int g  = threadIdx.x >> 6;
    int n  = blockIdx.x * 4 + g;
    if (n >= NNODE) return;
    int h  = tl >> 4;
    int c4 = tl * 4;
    int beg = g_offs[n], end = g_offs[n + 1];
    float ad = g_ad1[n * H1 + h];

    float wself = __expf(leakyr(g_as1[n * H1 + h] + ad));
    float4 hv = *(const float4*)&g_h1[(size_t)n * F1 + c4];
    float s0 = wself, s1 = 0.f, s2 = 0.f, s3 = 0.f;
    float4 a0 = make_float4(wself * hv.x, wself * hv.y, wself * hv.z, wself * hv.w);
    float4 a1 = make_float4(0.f, 0.f, 0.f, 0.f);
    float4 a2 = make_float4(0.f, 0.f, 0.f, 0.f);
    float4 a3 = make_float4(0.f, 0.f, 0.f, 0.f);

    int i = beg;
    for (; i + 3 < end; i += 4) {
        int sA = g_csr[i], sB = g_csr[i + 1], sC = g_csr[i + 2], sD = g_csr[i + 3];
        float wA = __expf(leakyr(g_as1[sA * H1 + h] + ad));
        float wB = __expf(leakyr(g_as1[sB * H1 + h] + ad));
        float wC = __expf(leakyr(g_as1[sC * H1 + h] + ad));
        float wD = __expf(leakyr(g_as1[sD * H1 + h] + ad));
        float4 hA = *(const float4*)&g_h1[(size_t)sA * F1 + c4];
        float4 hB = *(const float4*)&g_h1[(size_t)sB * F1 + c4];
        float4 hC = *(const float4*)&g_h1[(size_t)sC * F1 + c4];
        float4 hD = *(const float4*)&g_h1[(size_t)sD * F1 + c4];
        s0 += wA; s1 += wB; s2 += wC; s3 += wD;
        a0.x = fmaf(wA, hA.x, a0.x); a0.y = fmaf(wA, hA.y, a0.y);
        a0.z = fmaf(wA, hA.z, a0.z); a0.w = fmaf(wA, hA.w, a0.w);
        a1.x = fmaf(wB, hB.x, a1.x); a1.y = fmaf(wB, hB.y, a1.y);
        a1.z = fmaf(wB, hB.z, a1.z); a1.w = fmaf(wB, hB.w, a1.w);
        a2.x = fmaf(wC, hC.x, a2.x); a2.y = fmaf(wC, hC.y, a2.y);
        a2.z = fmaf(wC, hC.z, a2.z); a2.w = fmaf(wC, hC.w, a2.w);
        a3.x = fmaf(wD, hD.x, a3.x); a3.y = fmaf(wD, hD.y, a3.y);
        a3.z = fmaf(wD, hD.z, a3.z); a3.w = fmaf(wD, hD.w, a3.w);
    }
    for (; i < end; i++) {
        int sA = g_csr[i];
        float wA = __expf(leakyr(g_as1[sA * H1 + h] + ad));
        float4 hA = *(const float4*)&g_h1[(size_t)sA * F1 + c4];
        s0 += wA;
        a0.x = fmaf(wA, hA.x, a0.x); a0.y = fmaf(wA, hA.y, a0.y);
        a0.z = fmaf(wA, hA.z, a0.z); a0.w = fmaf(wA, hA.w, a0.w);
    }
    float inv = 1.f / (s0 + s1 + s2 + s3 + 1e-16f);
    float4 bb = *(const float4*)&b1[c4];
    float o0 = (a0.x + a1.x + a2.x + a3.x) * inv + bb.x;
    float o1 = (a0.y + a1.y + a2.y + a3.y) * inv + bb.y;
    float o2 = (a0.z + a1.z + a2.z + a3.z) * inv + bb.z;
    float o3 = (a0.w + a1.w + a2.w + a3.w) * inv + bb.w;
    float4 r;
    r.x = to_tf32((o0 > 0.f) ? o0 : (__expf(o0) - 1.f));
    r.y = to_tf32((o1 > 0.f) ? o1 : (__expf(o1) - 1.f));
    r.z = to_tf32((o2 > 0.f) ? o2 : (__expf(o2) - 1.f));
    r.w = to_tf32((o3 > 0.f) ? o3 : (__expf(o3) - 1.f));
    *(float4*)&g_hbuf[(size_t)n * F1 + c4] = r;
}

// ---------------- layer-2 aggregation (16 thr/node, 4-way ILP; R10-proven) --------
__global__ void __launch_bounds__(256)
agg2_kernel(const float* __restrict__ b2, float* __restrict__ out) {
    int tl = threadIdx.x & 15;
    int g  = threadIdx.x >> 4;
    int n  = blockIdx.x * 16 + g;
    if (n >= NNODE) return;
    int c4 = tl * 4;
    int beg = g_offs[n], end = g_offs[n + 1];
    float ad = g_ad2[n];

    float wself = __expf(leakyr(g_as2[n] + ad));
    float4 hv = *(const float4*)&g_h2[(size_t)n * C2 + c4];
    float s0 = wself, s1 = 0.f, s2 = 0.f, s3 = 0.f;
    float4 a0 = make_float4(wself * hv.x, wself * hv.y, wself * hv.z, wself * hv.w);
    float4 a1 = make_float4(0.f, 0.f, 0.f, 0.f);
    float4 a2 = make_float4(0.f, 0.f, 0.f, 0.f);
    float4 a3 = make_float4(0.f, 0.f, 0.f, 0.f);

    int i = beg;
    for (; i + 3 < end; i += 4) {
        int sA = g_csr[i], sB = g_csr[i + 1], sC = g_csr[i + 2], sD = g_csr[i + 3];
        float wA = __expf(leakyr(g_as2[sA] + ad));
        float wB = __expf(leakyr(g_as2[sB] + ad));
        float wC = __expf(leakyr(g_as2[sC] + ad));
        float wD = __expf(leakyr(g_as2[sD] + ad));
        float4 hA = *(const float4*)&g_h2[(size_t)sA * C2 + c4];
        float4 hB = *(const float4*)&g_h2[(size_t)sB * C2 + c4];
        float4 hC = *(const float4*)&g_h2[(size_t)sC * C2 + c4];
        float4 hD = *(const float4*)&g_h2[(size_t)sD * C2 + c4];
        s0 += wA; s1 += wB; s2 += wC; s3 += wD;
        a0.x = fmaf(wA, hA.x, a0.x); a0.y = fmaf(wA, hA.y, a0.y);
        a0.z = fmaf(wA, hA.z, a0.z); a0.w = fmaf(wA, hA.w, a0.w);
        a1.x = fmaf(wB, hB.x, a1.x); a1.y = fmaf(wB, hB.y, a1.y);
        a1.z = fmaf(wB, hB.z, a1.z); a1.w = fmaf(wB, hB.w, a1.w);
        a2.x = fmaf(wC, hC.x, a2.x); a2.y = fmaf(wC, hC.y, a2.y);
        a2.z = fmaf(wC, hC.z, a2.z); a2.w = fmaf(wC, hC.w, a2.w);
        a3.x = fmaf(wD, hD.x, a3.x); a3.y = fmaf(wD, hD.y, a3.y);
        a3.z = fmaf(wD, hD.z, a3.z); a3.w = fmaf(wD, hD.w, a3.w);
    }
    for (; i < end; i++) {
        int sA = g_csr[i];
        float wA = __expf(leakyr(g_as2[sA] + ad));
        float4 hA = *(const float4*)&g_h2[(size_t)sA * C2 + c4];
        s0 += wA;
        a0.x = fmaf(wA, hA.x, a0.x); a0.y = fmaf(wA, hA.y, a0.y);
        a0.z = fmaf(wA, hA.z, a0.z); a0.w = fmaf(wA, hA.w, a0.w);
    }
    float inv = 1.f / (s0 + s1 + s2 + s3 + 1e-16f);
    float4 bb = *(const float4*)&b2[c4];
    float o0 = (a0.x + a1.x + a2.x + a3.x) * inv + bb.x;
    float o1 = (a0.y + a1.y + a2.y + a3.y) * inv + bb.y;
    float o2 = (a0.z + a1.z + a2.z + a3.z) * inv + bb.z;
    float o3 = (a0.w + a1.w + a2.w + a3.w) * inv + bb.w;
    float4 r;
    r.x = (o0 > 0.f) ? o0 : (__expf(o0) - 1.f);
    r.y = (o1 > 0.f) ? o1 : (__expf(o1) - 1.f);
    r.z = (o2 > 0.f) ? o2 : (__expf(o2) - 1.f);
    r.w = (o3 > 0.f) ? o3 : (__expf(o3) - 1.f);
    *(float4*)&out[(size_t)n * C2 + c4] = r;
}

// ---------------- launch ----------------
extern "C" void kernel_launch(void* const* d_in, const int* in_sizes, int n_in,
                              void* d_out, int out_size) {
    const float* x    = (const float*)d_in[0];
    const int*   ei   = (const int*)d_in[1];
    const float* W1   = (const float*)d_in[2];
    const float* as1w = (const float*)d_in[3];
    const float* ad1w = (const float*)d_in[4];
    const float* b1   = (const float*)d_in[5];
    const float* W2   = (const float*)d_in[6];
    const float* as2w = (const float*)d_in[7];
    const float* ad2w = (const float*)d_in[8];
    const float* b2   = (const float*)d_in[9];
    float*       out  = (float*)d_out;

    (void)in_sizes; (void)n_in; (void)out_size;

    static cudaStream_t s2 = []() {
        cudaStream_t s; cudaStreamCreateWithFlags(&s, cudaStreamNonBlocking); return s;
    }();
    static cudaEvent_t evFork = []() {
        cudaEvent_t e; cudaEventCreateWithFlags(&e, cudaEventDisableTiming); return e;
    }();
    static cudaEvent_t evJoin = []() {
        cudaEvent_t e; cudaEventCreateWithFlags(&e, cudaEventDisableTiming); return e;
    }();

    // ---- fork: CSR build on s2 overlaps operand-rounding + GEMM1 on main ----
    cudaEventRecord(evFork, 0);
    cudaStreamWaitEvent(s2, evFork, 0);

    // my launches: 1=round_x 2=round_w 3=zero 4=GEMM1 (profiled by ncu slot #6)
    round_x_kernel<<<(NNODE * FIN / 4 + 255) / 256, 256>>>(x);
    round_w_kernel<<<(FIN * F1 + 255) / 256, 256>>>(W1, W2);
    zero_ints_kernel<<<(NNODE + 255) / 256, 256, 0, s2>>>();

    {
        dim3 grid(F1 / 128, M_PAD / 128);   // (2, 391)
        wmma_gemm_kernel<128, 64, 0><<<grid, 256>>>(NNODE, FIN);
    }

    count_deg_kernel<<<(NEDGE + 255) / 256, 256, 0, s2>>>(ei);
    scan_block_kernel<<<SCAN_NB, SCAN_T, 0, s2>>>();
    scan_add_kernel<<<SCAN_NB, SCAN_T, 0, s2>>>();
    scatter_kernel<<<(NEDGE + 255) / 256, 256, 0, s2>>>(ei);
    cudaEventRecord(evJoin, s2);

    attn_coeff_kernel<0><<<(NNODE * H1 + 7) / 8, 256>>>(as1w, ad1w);

    // ---- join: agg1 needs CSR + h1 + coeffs ----
    cudaStreamWaitEvent(0, evJoin, 0);
    agg1_kernel<<<(NNODE + 3) / 4, 256>>>(b1);

    // ---- layer 2 ----
    {
        dim3 grid(1, M_PAD / 128);          // (1, 391)
        wmma_gemm_kernel<64, 32, 1><<<grid, 256>>>(NNODE, F1);
    }
    attn_coeff_kernel<1><<<(NNODE + 7) / 8, 256>>>(as2w, ad2w);
    agg2_kernel<<<(NNODE + 15) / 16, 256>>>(b2, out);
}

// round 15
// speedup vs baseline: 1.2618x; 1.1703x over previous
#include <cuda_runtime.h>
#include <mma.h>
#include <math.h>
#include <stdint.h>

using namespace nvcuda;

// ---------------- problem constants ----------------
constexpr int NNODE = 50000;
constexpr int NEDGE = 800000;
constexpr int FIN   = 256;
constexpr int H1    = 4;
constexpr int F1    = 256;
constexpr int C2    = 64;
constexpr float SLOPE = 0.2f;
constexpr int M_PAD = 50048;   // 128 * 391

// ---------------- scratch ----------------
__device__ float g_w1r[FIN * F1];              // tf32-rounded W1
__device__ float g_w2r[F1 * C2];               // tf32-rounded W2
__device__ float g_h1[(size_t)M_PAD * F1];
__device__ float g_hbuf[(size_t)M_PAD * F1];
__device__ float g_h2[(size_t)M_PAD * C2];
__device__ float g_as1[NNODE * H1];
__device__ float g_ad1[NNODE * H1];
__device__ float g_as2[NNODE];
__device__ float g_ad2[NNODE];
__device__ int   g_deg[NNODE];
__device__ int   g_cur[NNODE];
__device__ int   g_offs[NNODE + 1];
__device__ int   g_bsums[64];
__device__ int   g_csr[NEDGE];

__device__ __forceinline__ float leakyr(float v) { return v > 0.f ? v : SLOPE * v; }

__device__ __forceinline__ float to_tf32(float x) {
    uint32_t r;
    asm("cvt.rna.tf32.f32 %0, %1;\n" : "=r"(r) : "f"(x));
    return __uint_as_float(r);
}

// ---------------- weight pre-rounding (tiny) ----------------
__global__ void round_w_kernel(const float* __restrict__ W1, const float* __restrict__ W2) {
    int i = blockIdx.x * blockDim.x + threadIdx.x;
    if (i < FIN * F1) g_w1r[i] = to_tf32(W1[i]);
    if (i < F1 * C2)  g_w2r[i] = to_tf32(W2[i]);
}

// ---------------- CSR construction (5 kernels) ----------------
__global__ void zero_ints_kernel() {
    int i = blockIdx.x * blockDim.x + threadIdx.x;
    if (i < NNODE) g_deg[i] = 0;
}

__global__ void count_deg_kernel(const int* __restrict__ ei) {
    int e = blockIdx.x * blockDim.x + threadIdx.x;
    if (e < NEDGE) {
        int d = ei[NEDGE + e];
        if (d >= 0 && d < NNODE) atomicAdd(&g_deg[d], 1);
    }
}

constexpr int SCAN_T = 1024;
constexpr int SCAN_NB = (NNODE + SCAN_T - 1) / SCAN_T;  // 49

__global__ void scan_block_kernel() {
    __shared__ int sh[SCAN_T];
    int gid = blockIdx.x * SCAN_T + threadIdx.x;
    int v = (gid < NNODE) ? g_deg[gid] : 0;
    sh[threadIdx.x] = v;
    __syncthreads();
    for (int off = 1; off < SCAN_T; off <<= 1) {
        int t = (threadIdx.x >= off) ? sh[threadIdx.x - off] : 0;
        __syncthreads();
        sh[threadIdx.x] += t;
        __syncthreads();
    }
    if (gid < NNODE) g_offs[gid] = sh[threadIdx.x] - v;
    if (threadIdx.x == SCAN_T - 1) g_bsums[blockIdx.x] = sh[threadIdx.x];
}

__global__ void scan_add_kernel() {
    __shared__ int base_sh;
    int t = threadIdx.x;
    if (t == 0) {
        int s = 0;
        for (int i = 0; i < blockIdx.x; i++) s += g_bsums[i];
        base_sh = s;
    }
    __syncthreads();
    int gid = blockIdx.x * SCAN_T + t;
    if (gid < NNODE) {
        int v = g_offs[gid] + base_sh;
        g_offs[gid] = v;
        g_cur[gid] = v;
    }
    if (gid == 0) g_offs[NNODE] = NEDGE;
}

__global__ void scatter_kernel(const int* __restrict__ ei) {
    int e = blockIdx.x * blockDim.x + threadIdx.x;
    if (e < NEDGE) {
        int d = ei[NEDGE + e];
        int s = ei[e];
        if (d >= 0 && d < NNODE && s >= 0 && s < NNODE) {
            int p = atomicAdd(&g_cur[d], 1);
            if (p >= 0 && p < NEDGE) g_csr[p] = s;
        }
    }
}

// ---------------- tf32 wmma GEMM: 128 threads, 4 warps, 64xWN warp tiles --------
// BM=128, BK=16. Warp grid 2x2: warpM=wid&1 (64 rows), warpN=wid>>1 (WN cols).
// MI=4 so 4*NI MMAs per (4+NI) fragment loads -> 2x less LDS per MMA than 32x64.
// A (x or g_hbuf) cvt'd to tf32 in-fragment; B (weights) pre-rounded.
// MODE 0: A=x arg,  B=g_w1r, C=g_h1, BN=128, WN=64 (NI=4).
// MODE 1: A=g_hbuf, B=g_w2r, C=g_h2, BN=64,  WN=32 (NI=2).
template <int BN, int WN, int MODE>
__global__ void __launch_bounds__(128, 2)
wmma_gemm_kernel(const float* __restrict__ Aarg, int M, int K) {
    constexpr int BM = 128, BK = 16, WM = 64;
    constexpr int MI = WM / 16;       // 4
    constexpr int NI = WN / 16;       // 4 or 2
    constexpr int LDA = BK + 4;       // 20 floats

    const float* __restrict__ A = (MODE == 0) ? Aarg : g_hbuf;
    const float* __restrict__ B = (MODE == 0) ? g_w1r : g_w2r;
    float* __restrict__ C = (MODE == 0) ? g_h1 : g_h2;

    __shared__ float As[2][BM][LDA];   // 20 KB
    __shared__ float Bs[2][BK][BN];    // 16 / 8 KB

    int tid = threadIdx.x;             // 0..127
    int wid = tid >> 5;                // 0..3
    int warpM = wid & 1;
    int warpN = wid >> 1;
    int rowBase = blockIdx.y * BM;
    int colBase = blockIdx.x * BN;
    int Nt = BN * gridDim.x;

    wmma::fragment<wmma::accumulator, 16, 16, 8, float> c[MI][NI];
#pragma unroll
    for (int i = 0; i < MI; i++)
#pragma unroll
        for (int j = 0; j < NI; j++) wmma::fill_fragment(c[i][j], 0.f);

    constexpr int B_F4 = BK * BN / 4;      // 512 or 256
    constexpr int B_F4PR = BN / 4;

    auto issue = [&](int buf, int k0) {
#pragma unroll
        for (int li = 0; li < 4; li++) {           // A: 512 float4 / 128 thr
            int f4 = tid + li * 128;
            int row = f4 >> 2;
            int col = (f4 & 3) * 4;
            int rg = rowBase + row;
            const float* src = &A[(size_t)(rg < M ? rg : 0) * K + k0 + col];
            uint32_t dst = (uint32_t)__cvta_generic_to_shared(&As[buf][row][col]);
            int sz = (rg < M) ? 16 : 0;
            asm volatile("cp.async.cg.shared.global [%0], [%1], 16, %2;\n"
                         :: "r"(dst), "l"(src), "r"(sz));
        }
#pragma unroll
        for (int li = 0; li < B_F4 / 128; li++) {  // B: 512/256 float4
            int f4 = tid + li * 128;
            int row = f4 / B_F4PR;
            int col = (f4 % B_F4PR) * 4;
            const float* src = &B[(size_t)(k0 + row) * Nt + colBase + col];
            uint32_t dst = (uint32_t)__cvta_generic_to_shared(&Bs[buf][row][col]);
            asm volatile("cp.async.cg.shared.global [%0], [%1], 16;\n"
                         :: "r"(dst), "l"(src));
        }
        asm volatile("cp.async.commit_group;\n");
    };

    int NT = K / BK;
    issue(0, 0);

    for (int kt = 0; kt < NT; kt++) {
        if (kt + 1 < NT) {
            issue((kt + 1) & 1, (kt + 1) * BK);
            asm volatile("cp.async.wait_group 1;\n");
        } else {
            asm volatile("cp.async.wait_group 0;\n");
        }
        __syncthreads();
        int buf = kt & 1;

#pragma unroll
        for (int kk = 0; kk < BK; kk += 8) {
            wmma::fragment<wmma::matrix_a, 16, 16, 8, wmma::precision::tf32, wmma::row_major> a[MI];
            wmma::fragment<wmma::matrix_b, 16, 16, 8, wmma::precision::tf32, wmma::row_major> b[NI];
#pragma unroll
            for (int i = 0; i < MI; i++) {
                wmma::load_matrix_sync(a[i], &As[buf][warpM * WM + i * 16][kk], LDA);
#pragma unroll
                for (int t = 0; t < a[i].num_elements; t++) a[i].x[t] = to_tf32(a[i].x[t]);
            }
#pragma unroll
            for (int j = 0; j < NI; j++)
                wmma::load_matrix_sync(b[j], &Bs[buf][kk][warpN * WN + j * 16], BN);
#pragma unroll
            for (int i = 0; i < MI; i++)
#pragma unroll
                for (int j = 0; j < NI; j++)
                    wmma::mma_sync(c[i][j], a[i], b[j], c[i][j]);
        }
        __syncthreads();
    }

    int ldc = Nt;
#pragma unroll
    for (int i = 0; i < MI; i++)
#pragma unroll
        for (int j = 0; j < NI; j++) {
            int r = rowBase + warpM * WM + i * 16;
            int cc = colBase + warpN * WN + j * 16;
            wmma::store_matrix_sync(&C[(size_t)r * ldc + cc], c[i][j], ldc, wmma::mem_row_major);
        }
}

// ---------------- attention coefficients (warp per (node,head), coalesced) -------
template <int L>
__global__ void attn_coeff_kernel(const float* __restrict__ atts,
                                  const float* __restrict__ attd) {
    const float* __restrict__ h = (L == 0) ? g_h1 : g_h2;
    float* __restrict__ oS = (L == 0) ? g_as1 : g_as2;
    float* __restrict__ oD = (L == 0) ? g_ad1 : g_ad2;
    const int H = (L == 0) ? H1 : 1;

    int w = (blockIdx.x * blockDim.x + threadIdx.x) >> 5;
    int lane = threadIdx.x & 31;
    if (w >= NNODE * H) return;
    int hh = w % H;
    const float* hp = h + (size_t)w * 64;

    float x1 = hp[lane], x2 = hp[lane + 32];
    float ss = x1 * atts[hh * 64 + lane] + x2 * atts[hh * 64 + lane + 32];
    float sd = x1 * attd[hh * 64 + lane] + x2 * attd[hh * 64 + lane + 32];
#pragma unroll
    for (int o = 16; o; o >>= 1) {
        ss += __shfl_xor_sync(0xFFFFFFFFu, ss, o);
        sd += __shfl_xor_sync(0xFFFFFFFFu, sd, o);
    }
    if (lane == 0) { oS[w] = ss; oD[w] = sd; }
}

// ---------------- layer-1 aggregation (R10-proven) ----------------
__global__ void __launch_bounds__(256)
agg1_kernel(const float* __restrict__ b1) {
    int tl = threadIdx.x & 63;
    int g  = threadIdx.x >> 6;
    int n  = blockIdx.x * 4 + g;
    if (n >= NNODE) return;
    int h  = tl >> 4;
    int c4 = tl * 4;
    int beg = g_offs[n], end = g_offs[n + 1];
    float ad = g_ad1[n * H1 + h];

    float wself = __expf(leakyr(g_as1[n * H1 + h] + ad));
    float4 hv = *(const float4*)&g_h1[(size_t)n * F1 + c4];
    float s0 = wself, s1 = 0.f, s2 = 0.f, s3 = 0.f;
    float4 a0 = make_float4(wself * hv.x, wself * hv.y, wself * hv.z, wself * hv.w);
    float4 a1 = make_float4(0.f, 0.f, 0.f, 0.f);
    float4 a2 = make_float4(0.f, 0.f, 0.f, 0.f);
    float4 a3 = make_float4(0.f, 0.f, 0.f, 0.f);

    int i = beg;
    for (; i + 3 < end; i += 4) {
        int sA = g_csr[i], sB = g_csr[i + 1], sC = g_csr[i + 2], sD = g_csr[i + 3];
        float wA = __expf(leakyr(g_as1[sA * H1 + h] + ad));
        float wB = __expf(leakyr(g_as1[sB * H1 + h] + ad));
        float wC = __expf(leakyr(g_as1[sC * H1 + h] + ad));
        float wD = __expf(leakyr(g_as1[sD * H1 + h] + ad));
        float4 hA = *(const float4*)&g_h1[(size_t)sA * F1 + c4];
        float4 hB = *(const float4*)&g_h1[(size_t)sB * F1 + c4];
        float4 hC = *(const float4*)&g_h1[(size_t)sC * F1 + c4];
        float4 hD = *(const float4*)&g_h1[(size_t)sD * F1 + c4];
        s0 += wA; s1 += wB; s2 += wC; s3 += wD;
        a0.x = fmaf(wA, hA.x, a0.x); a0.y = fmaf(wA, hA.y, a0.y);
        a0.z = fmaf(wA, hA.z, a0.z); a0.w = fmaf(wA, hA.w, a0.w);
        a1.x = fmaf(wB, hB.x, a1.x); a1.y = fmaf(wB, hB.y, a1.y);
        a1.z = fmaf(wB, hB.z, a1.z); a1.w = fmaf(wB, hB.w, a1.w);
        a2.x = fmaf(wC, hC.x, a2.x); a2.y = fmaf(wC, hC.y, a2.y);
        a2.z = fmaf(wC, hC.z, a2.z); a2.w = fmaf(wC, hC.w, a2.w);
        a3.x = fmaf(wD, hD.x, a3.x); a3.y = fmaf(wD, hD.y, a3.y);
        a3.z = fmaf(wD, hD.z, a3.z); a3.w = fmaf(wD, hD.w, a3.w);
    }
    for (; i < end; i++) {
        int sA = g_csr[i];
        float wA = __expf(leakyr(g_as1[sA * H1 + h] + ad));
        float4 hA = *(const float4*)&g_h1[(size_t)sA * F1 + c4];
        s0 += wA;
        a0.x = fmaf(wA, hA.x, a0.x); a0.y = fmaf(wA, hA.y, a0.y);
        a0.z = fmaf(wA, hA.z, a0.z); a0.w = fmaf(wA, hA.w, a0.w);
    }
    float inv = 1.f / (s0 + s1 + s2 + s3 + 1e-16f);
    float4 bb = *(const float4*)&b1[c4];
    float o0 = (a0.x + a1.x + a2.x + a3.x) * inv + bb.x;
    float o1 = (a0.y + a1.y + a2.y + a3.y) * inv + bb.y;
    float o2 = (a0.z + a1.z + a2.z + a3.z) * inv + bb.z;
    float o3 = (a0.w + a1.w + a2.w + a3.w) * inv + bb.w;
    float4 r;
    r.x = (o0 > 0.f) ? o0 : (__expf(o0) - 1.f);
    r.y = (o1 > 0.f) ? o1 : (__expf(o1) - 1.f);
    r.z = (o2 > 0.f) ? o2 : (__expf(o2) - 1.f);
    r.w = (o3 > 0.f) ? o3 : (__expf(o3) - 1.f);
    *(float4*)&g_hbuf[(size_t)n * F1 + c4] = r;
}

// ---------------- layer-2 aggregation (16 thr/node, 4-way ILP; R10-proven) --------
__global__ void __launch_bounds__(256)
agg2_kernel(const float* __restrict__ b2, float* __restrict__ out) {
    int tl = threadIdx.x & 15;
    int g  = threadIdx.x >> 4;
    int n  = blockIdx.x * 16 + g;
    if (n >= NNODE) return;
    int c4 = tl * 4;
    int beg = g_offs[n], end = g_offs[n + 1];
    float ad = g_ad2[n];

    float wself = __expf(leakyr(g_as2[n] + ad));
    float4 hv = *(const float4*)&g_h2[(size_t)n * C2 + c4];
    float s0 = wself, s1 = 0.f, s2 = 0.f, s3 = 0.f;
    float4 a0 = make_float4(wself * hv.x, wself * hv.y, wself * hv.z, wself * hv.w);
    float4 a1 = make_float4(0.f, 0.f, 0.f, 0.f);
    float4 a2 = make_float4(0.f, 0.f, 0.f, 0.f);
    float4 a3 = make_float4(0.f, 0.f, 0.f, 0.f);

    int i = beg;
    for (; i + 3 < end; i += 4) {
        int sA = g_csr[i], sB = g_csr[i + 1], sC = g_csr[i + 2], sD = g_csr[i + 3];
        float wA = __expf(leakyr(g_as2[sA] + ad));
        float wB = __expf(leakyr(g_as2[sB] + ad));
        float wC = __expf(leakyr(g_as2[sC] + ad));
        float wD = __expf(leakyr(g_as2[sD] + ad));
        float4 hA = *(const float4*)&g_h2[(size_t)sA * C2 + c4];
        float4 hB = *(const float4*)&g_h2[(size_t)sB * C2 + c4];
        float4 hC = *(const float4*)&g_h2[(size_t)sC * C2 + c4];
        float4 hD = *(const float4*)&g_h2[(size_t)sD * C2 + c4];
        s0 += wA; s1 += wB; s2 += wC; s3 += wD;
        a0.x = fmaf(wA, hA.x, a0.x); a0.y = fmaf(wA, hA.y, a0.y);
        a0.z = fmaf(wA, hA.z, a0.z); a0.w = fmaf(wA, hA.w, a0.w);
        a1.x = fmaf(wB, hB.x, a1.x); a1.y = fmaf(wB, hB.y, a1.y);
        a1.z = fmaf(wB, hB.z, a1.z); a1.w = fmaf(wB, hB.w, a1.w);
        a2.x = fmaf(wC, hC.x, a2.x); a2.y = fmaf(wC, hC.y, a2.y);
        a2.z = fmaf(wC, hC.z, a2.z); a2.w = fmaf(wC, hC.w, a2.w);
        a3.x = fmaf(wD, hD.x, a3.x); a3.y = fmaf(wD, hD.y, a3.y);
        a3.z = fmaf(wD, hD.z, a3.z); a3.w = fmaf(wD, hD.w, a3.w);
    }
    for (; i < end; i++) {
        int sA = g_csr[i];
        float wA = __expf(leakyr(g_as2[sA] + ad));
        float4 hA = *(const float4*)&g_h2[(size_t)sA * C2 + c4];
        s0 += wA;
        a0.x = fmaf(wA, hA.x, a0.x); a0.y = fmaf(wA, hA.y, a0.y);
        a0.z = fmaf(wA, hA.z, a0.z); a0.w = fmaf(wA, hA.w, a0.w);
    }
    float inv = 1.f / (s0 + s1 + s2 + s3 + 1e-16f);
    float4 bb = *(const float4*)&b2[c4];
    float o0 = (a0.x + a1.x + a2.x + a3.x) * inv + bb.x;
    float o1 = (a0.y + a1.y + a2.y + a3.y) * inv + bb.y;
    float o2 = (a0.z + a1.z + a2.z + a3.z) * inv + bb.z;
    float o3 = (a0.w + a1.w + a2.w + a3.w) * inv + bb.w;
    float4 r;
    r.x = (o0 > 0.f) ? o0 : (__expf(o0) - 1.f);
    r.y = (o1 > 0.f) ? o1 : (__expf(o1) - 1.f);
    r.z = (o2 > 0.f) ? o2 : (__expf(o2) - 1.f);
    r.w = (o3 > 0.f) ? o3 : (__expf(o3) - 1.f);
    *(float4*)&out[(size_t)n * C2 + c4] = r;
}

// ---------------- launch ----------------
extern "C" void kernel_launch(void* const* d_in, const int* in_sizes, int n_in,
                              void* d_out, int out_size) {
    const float* x    = (const float*)d_in[0];
    const int*   ei   = (const int*)d_in[1];
    const float* W1   = (const float*)d_in[2];
    const float* as1w = (const float*)d_in[3];
    const float* ad1w = (const float*)d_in[4];
    const float* b1   = (const float*)d_in[5];
    const float* W2   = (const float*)d_in[6];
    const float* as2w = (const float*)d_in[7];
    const float* ad2w = (const float*)d_in[8];
    const float* b2   = (const float*)d_in[9];
    float*       out  = (float*)d_out;

    (void)in_sizes; (void)n_in; (void)out_size;

    static cudaStream_t s2 = []() {
        cudaStream_t s; cudaStreamCreateWithFlags(&s, cudaStreamNonBlocking); return s;
    }();
    static cudaEvent_t evFork = []() {
        cudaEvent_t e; cudaEventCreateWithFlags(&e, cudaEventDisableTiming); return e;
    }();
    static cudaEvent_t evJoin = []() {
        cudaEvent_t e; cudaEventCreateWithFlags(&e, cudaEventDisableTiming); return e;
    }();

    // ---- fork: CSR build on s2 overlaps weight-rounding + GEMM1 on main ----
    cudaEventRecord(evFork, 0);
    cudaStreamWaitEvent(s2, evFork, 0);

    // my launches: 1=round_w 2=zero(s2) 3=count(s2) 4=GEMM1 (ncu slot #6)
    round_w_kernel<<<(FIN * F1 + 255) / 256, 256>>>(W1, W2);
    zero_ints_kernel<<<(NNODE + 255) / 256, 256, 0, s2>>>();
    count_deg_kernel<<<(NEDGE + 255) / 256, 256, 0, s2>>>(ei);

    {
        dim3 grid(F1 / 128, M_PAD / 128);   // (2, 391)
        wmma_gemm_kernel<128, 64, 0><<<grid, 128>>>(x, NNODE, FIN);
    }

    scan_block_kernel<<<SCAN_NB, SCAN_T, 0, s2>>>();
    scan_add_kernel<<<SCAN_NB, SCAN_T, 0, s2>>>();
    scatter_kernel<<<(NEDGE + 255) / 256, 256, 0, s2>>>(ei);
    cudaEventRecord(evJoin, s2);

    attn_coeff_kernel<0><<<(NNODE * H1 + 7) / 8, 256>>>(as1w, ad1w);

    // ---- join: agg1 needs CSR + h1 + coeffs ----
    cudaStreamWaitEvent(0, evJoin, 0);
    agg1_kernel<<<(NNODE + 3) / 4, 256>>>(b1);

    // ---- layer 2 ----
    {
        dim3 grid(1, M_PAD / 128);          // (1, 391)
        wmma_gemm_kernel<64, 32, 1><<<grid, 128>>>(nullptr, NNODE, F1);
    }
    attn_coeff_kernel<1><<<(NNODE + 7) / 8, 256>>>(as2w, ad2w);
    agg2_kernel<<<(NNODE + 15) / 16, 256>>>(b2, out);
}